// round 1
// baseline (speedup 1.0000x reference)
#include <cuda_runtime.h>

// SplitMLP: B=128, C=16, V=32, H=64, O=4, G=10000
// y[b,g,o] = b2[g,o] + sum_j W2[g,o,j] * relu( b1[g,j]
//            + sum_c day[b,c]*W1_day[g,j,c] + sum_v items[b,g,v]*W1_var[g,j,v] )
//
// One CTA per group g; 128 threads = 128 batch rows.
// All per-group operands staged in padded SMEM; inner j-loop fully unrolled
// with 64 independent accumulators (max FFMA ILP); outer k-loops rolled to
// keep code size small.

#define BB 128
#define CC 16
#define VV 32
#define HH 64
#define OO 4
#define GG 10000

#define WSTR 68   // padded j-stride for transposed W1 tiles (mult of 4, !mult of 32)

__global__ __launch_bounds__(128) void splitmlp_kernel(
    const float* __restrict__ day,     // (B, C)
    const float* __restrict__ items,   // (B, G, V)
    const float* __restrict__ W1_day,  // (G, H, C)
    const float* __restrict__ W1_var,  // (G, H, V)
    const float* __restrict__ b1,      // (G, H)
    const float* __restrict__ W2,      // (G, O, H)
    const float* __restrict__ b2,      // (G, O)
    float* __restrict__ out)           // (B, G, O)
{
    __shared__ float s_w1d[CC * WSTR];      // [c][j], padded
    __shared__ float s_w1v[VV * WSTR];      // [v][j], padded
    __shared__ float s_w2[OO * HH];         // [o][j]
    __shared__ float s_b1[HH];
    __shared__ float s_b2[OO];
    __shared__ float s_day[BB * 17];        // [b][c], padded
    __shared__ float s_items[BB * 33];      // [b][v], padded

    const int g   = blockIdx.x;
    const int tid = threadIdx.x;

    // ---- cooperative staging ----
    // W1_day (g): 1024 floats, store transposed [c][j]
    {
        const float* p = W1_day + g * (HH * CC);
        #pragma unroll
        for (int i = tid; i < HH * CC; i += 128) {
            int j = i >> 4, c = i & 15;
            s_w1d[c * WSTR + j] = p[i];
        }
    }
    // W1_var (g): 2048 floats, store transposed [v][j]
    {
        const float* p = W1_var + g * (HH * VV);
        #pragma unroll
        for (int i = tid; i < HH * VV; i += 128) {
            int j = i >> 5, v = i & 31;
            s_w1v[v * WSTR + j] = p[i];
        }
    }
    // W2 (g): 256 floats, natural layout [o][j]
    {
        const float* p = W2 + g * (OO * HH);
        #pragma unroll
        for (int i = tid; i < OO * HH; i += 128) s_w2[i] = p[i];
    }
    if (tid < HH) s_b1[tid] = b1[g * HH + tid];
    if (tid < OO) s_b2[tid] = b2[g * OO + tid];

    // day: 128x16 floats via float4
    {
        const float4* p4 = (const float4*)day;
        #pragma unroll
        for (int i = tid; i < (BB * CC) / 4; i += 128) {
            int b = i >> 2, q = i & 3;
            float4 t = p4[i];
            float* d = &s_day[b * 17 + q * 4];
            d[0] = t.x; d[1] = t.y; d[2] = t.z; d[3] = t.w;
        }
    }
    // items[:, g, :]: 128x32 floats via float4
    {
        const float4* p4 = (const float4*)items;
        #pragma unroll
        for (int i = tid; i < (BB * VV) / 4; i += 128) {
            int b = i >> 3, q = i & 7;
            float4 t = p4[(size_t)(b * GG + g) * 8 + q];
            float* d = &s_items[b * 33 + q * 4];
            d[0] = t.x; d[1] = t.y; d[2] = t.z; d[3] = t.w;
        }
    }
    __syncthreads();

    // ---- per-thread compute: one batch row ----
    const int b = tid;
    float h[HH];
    #pragma unroll
    for (int j = 0; j < HH; ++j) h[j] = s_b1[j];

    // fc1 day part
    #pragma unroll 1
    for (int c = 0; c < CC; ++c) {
        float dc = s_day[b * 17 + c];
        const float4* w = (const float4*)&s_w1d[c * WSTR];
        #pragma unroll
        for (int j4 = 0; j4 < HH / 4; ++j4) {
            float4 wv = w[j4];
            h[4 * j4 + 0] = fmaf(dc, wv.x, h[4 * j4 + 0]);
            h[4 * j4 + 1] = fmaf(dc, wv.y, h[4 * j4 + 1]);
            h[4 * j4 + 2] = fmaf(dc, wv.z, h[4 * j4 + 2]);
            h[4 * j4 + 3] = fmaf(dc, wv.w, h[4 * j4 + 3]);
        }
    }
    // fc1 items part
    #pragma unroll 1
    for (int v = 0; v < VV; ++v) {
        float iv = s_items[b * 33 + v];
        const float4* w = (const float4*)&s_w1v[v * WSTR];
        #pragma unroll
        for (int j4 = 0; j4 < HH / 4; ++j4) {
            float4 wv = w[j4];
            h[4 * j4 + 0] = fmaf(iv, wv.x, h[4 * j4 + 0]);
            h[4 * j4 + 1] = fmaf(iv, wv.y, h[4 * j4 + 1]);
            h[4 * j4 + 2] = fmaf(iv, wv.z, h[4 * j4 + 2]);
            h[4 * j4 + 3] = fmaf(iv, wv.w, h[4 * j4 + 3]);
        }
    }
    // ReLU
    #pragma unroll
    for (int j = 0; j < HH; ++j) h[j] = fmaxf(h[j], 0.0f);

    // fc2: 4 outputs, two partial accumulators each to shorten RAW chains
    float acc0[OO], acc1[OO];
    #pragma unroll
    for (int o = 0; o < OO; ++o) { acc0[o] = s_b2[o]; acc1[o] = 0.0f; }
    #pragma unroll
    for (int o = 0; o < OO; ++o) {
        const float4* w = (const float4*)&s_w2[o * HH];
        #pragma unroll
        for (int j4 = 0; j4 < HH / 4; ++j4) {
            float4 wv = w[j4];
            acc0[o] = fmaf(h[4 * j4 + 0], wv.x, acc0[o]);
            acc1[o] = fmaf(h[4 * j4 + 1], wv.y, acc1[o]);
            acc0[o] = fmaf(h[4 * j4 + 2], wv.z, acc0[o]);
            acc1[o] = fmaf(h[4 * j4 + 3], wv.w, acc1[o]);
        }
    }

    float4 res;
    res.x = acc0[0] + acc1[0];
    res.y = acc0[1] + acc1[1];
    res.z = acc0[2] + acc1[2];
    res.w = acc0[3] + acc1[3];
    ((float4*)out)[(size_t)b * GG + g] = res;
}

extern "C" void kernel_launch(void* const* d_in, const int* in_sizes, int n_in,
                              void* d_out, int out_size) {
    const float* day    = (const float*)d_in[0];
    const float* items  = (const float*)d_in[1];
    const float* W1_day = (const float*)d_in[2];
    const float* W1_var = (const float*)d_in[3];
    const float* b1     = (const float*)d_in[4];
    const float* W2     = (const float*)d_in[5];
    const float* b2     = (const float*)d_in[6];
    float* out = (float*)d_out;

    splitmlp_kernel<<<GG, 128>>>(day, items, W1_day, W1_var, b1, W2, b2, out);
}

// round 3
// speedup vs baseline: 1.2921x; 1.2921x over previous
#include <cuda_runtime.h>

// SplitMLP: B=128, C=16, V=32, H=64, O=4, G=10000
// One CTA per group. Warp w owns hidden tile j in [16w,16w+16); lane l owns
// batch rows {l, l+32, l+64, l+96}. 64 accumulators/thread, 5 LDS.128 per
// k-step for 64 FFMA. fc2 via SMEM round-trip of h (overlaid on W1/act).

#define BB 128
#define CC 16
#define VV 32
#define KK 48        // C + V
#define HH 64
#define OO 4
#define GG 10000

#define W1S 68       // k-row stride of staged W1 [k][j]
#define ACTS 52      // row stride of combined activations [b][k] (mult of 4, 13 odd)
#define HS 68        // row stride of staged h [b][j]

// overlay region: phase1 = W1 (48*68=3264) + ACT (128*52=6656) = 9920 floats
//                 phase2 = H (128*68=8704) floats
#define S_W1_OFF 0
#define S_ACT_OFF 3264
#define S_BUF_FLOATS 9920

__global__ __launch_bounds__(128, 4) void splitmlp_kernel(
    const float* __restrict__ day,     // (B, C)
    const float* __restrict__ items,   // (B, G, V)
    const float* __restrict__ W1_day,  // (G, H, C)
    const float* __restrict__ W1_var,  // (G, H, V)
    const float* __restrict__ b1,      // (G, H)
    const float* __restrict__ W2,      // (G, O, H)
    const float* __restrict__ b2,      // (G, O)
    float* __restrict__ out)           // (B, G, O)
{
    __shared__ float s_buf[S_BUF_FLOATS];
    __shared__ float s_w2[OO * HH];
    __shared__ float s_b1[HH];
    __shared__ float s_b2[OO];

    float* const S_W1  = s_buf + S_W1_OFF;
    float* const S_ACT = s_buf + S_ACT_OFF;
    float* const S_H   = s_buf;            // phase-2 overlay

    const int g     = blockIdx.x;
    const int tid   = threadIdx.x;
    const int lane  = tid & 31;
    const int wj    = tid >> 5;
    const int jbase = wj * 16;

    // ---- staging ----
    // W1_day (g): [j][c] -> S_W1[c][j]
    {
        const float* p = W1_day + g * (HH * CC);
        #pragma unroll
        for (int i = tid; i < HH * CC; i += 128) {
            int j = i >> 4, c = i & 15;
            S_W1[c * W1S + j] = p[i];
        }
    }
    // W1_var (g): [j][v] -> S_W1[16+v][j]
    {
        const float* p = W1_var + g * (HH * VV);
        #pragma unroll
        for (int i = tid; i < HH * VV; i += 128) {
            int j = i >> 5, v = i & 31;
            S_W1[(CC + v) * W1S + j] = p[i];
        }
    }
    // W2 (g)
    {
        const float* p = W2 + g * (OO * HH);
        #pragma unroll
        for (int i = tid; i < OO * HH; i += 128) s_w2[i] = p[i];
    }
    if (tid < HH) s_b1[tid] = b1[g * HH + tid];
    if (tid < OO) s_b2[tid] = b2[g * OO + tid];

    // day -> S_ACT[b][0..15]
    {
        const float4* p4 = (const float4*)day;
        #pragma unroll
        for (int i = tid; i < (BB * CC) / 4; i += 128) {
            int b = i >> 2, q = i & 3;
            *(float4*)&S_ACT[b * ACTS + q * 4] = p4[i];
        }
    }
    // items[:, g, :] -> S_ACT[b][16..47]
    {
        const float4* p4 = (const float4*)items;
        #pragma unroll
        for (int i = tid; i < (BB * VV) / 4; i += 128) {
            int b = i >> 3, q = i & 7;
            *(float4*)&S_ACT[b * ACTS + CC + q * 4] =
                p4[(size_t)(b * GG + g) * 8 + q];
        }
    }
    __syncthreads();

    // ---- fc1: h[row][jj], row r -> batch b = lane + 32r, jj -> j = jbase+jj ----
    float h[4][16];
    #pragma unroll
    for (int j4 = 0; j4 < 4; ++j4) {
        float4 bv = *(const float4*)&s_b1[jbase + j4 * 4];
        #pragma unroll
        for (int r = 0; r < 4; ++r) {
            h[r][j4 * 4 + 0] = bv.x;
            h[r][j4 * 4 + 1] = bv.y;
            h[r][j4 * 4 + 2] = bv.z;
            h[r][j4 * 4 + 3] = bv.w;
        }
    }

    #pragma unroll 1
    for (int k4 = 0; k4 < KK; k4 += 4) {
        float a[4][4];
        #pragma unroll
        for (int r = 0; r < 4; ++r) {
            float4 t = *(const float4*)&S_ACT[(lane + 32 * r) * ACTS + k4];
            a[r][0] = t.x; a[r][1] = t.y; a[r][2] = t.z; a[r][3] = t.w;
        }
        #pragma unroll
        for (int kk = 0; kk < 4; ++kk) {
            const float* wrow = &S_W1[(k4 + kk) * W1S + jbase];
            #pragma unroll
            for (int j4 = 0; j4 < 4; ++j4) {
                float4 wv = *(const float4*)&wrow[j4 * 4];
                #pragma unroll
                for (int r = 0; r < 4; ++r) {
                    h[r][j4 * 4 + 0] = fmaf(a[r][kk], wv.x, h[r][j4 * 4 + 0]);
                    h[r][j4 * 4 + 1] = fmaf(a[r][kk], wv.y, h[r][j4 * 4 + 1]);
                    h[r][j4 * 4 + 2] = fmaf(a[r][kk], wv.z, h[r][j4 * 4 + 2]);
                    h[r][j4 * 4 + 3] = fmaf(a[r][kk], wv.w, h[r][j4 * 4 + 3]);
                }
            }
        }
    }

    // ---- ReLU + store h to SMEM (overlay; must sync before overwrite) ----
    __syncthreads();
    #pragma unroll
    for (int r = 0; r < 4; ++r) {
        int b = lane + 32 * r;
        #pragma unroll
        for (int j4 = 0; j4 < 4; ++j4) {
            float4 t;
            t.x = fmaxf(h[r][j4 * 4 + 0], 0.0f);
            t.y = fmaxf(h[r][j4 * 4 + 1], 0.0f);
            t.z = fmaxf(h[r][j4 * 4 + 2], 0.0f);
            t.w = fmaxf(h[r][j4 * 4 + 3], 0.0f);
            *(float4*)&S_H[b * HS + jbase + j4 * 4] = t;
        }
    }
    __syncthreads();

    // ---- fc2: thread tid = batch row ----
    float hr[64];
    #pragma unroll
    for (int j4 = 0; j4 < 16; ++j4) {
        float4 t = *(const float4*)&S_H[tid * HS + j4 * 4];
        hr[4 * j4 + 0] = t.x; hr[4 * j4 + 1] = t.y;
        hr[4 * j4 + 2] = t.z; hr[4 * j4 + 3] = t.w;
    }

    float res[OO];
    #pragma unroll
    for (int o = 0; o < OO; ++o) {
        float a0 = s_b2[o], a1 = 0.0f, a2 = 0.0f, a3 = 0.0f;
        const float* w = &s_w2[o * HH];
        #pragma unroll
        for (int j4 = 0; j4 < 16; ++j4) {
            float4 wv = *(const float4*)&w[j4 * 4];
            a0 = fmaf(hr[4 * j4 + 0], wv.x, a0);
            a1 = fmaf(hr[4 * j4 + 1], wv.y, a1);
            a2 = fmaf(hr[4 * j4 + 2], wv.z, a2);
            a3 = fmaf(hr[4 * j4 + 3], wv.w, a3);
        }
        res[o] = (a0 + a1) + (a2 + a3);
    }

    float4 r4;
    r4.x = res[0]; r4.y = res[1]; r4.z = res[2]; r4.w = res[3];
    ((float4*)out)[(size_t)tid * GG + g] = r4;
}

extern "C" void kernel_launch(void* const* d_in, const int* in_sizes, int n_in,
                              void* d_out, int out_size) {
    const float* day    = (const float*)d_in[0];
    const float* items  = (const float*)d_in[1];
    const float* W1_day = (const float*)d_in[2];
    const float* W1_var = (const float*)d_in[3];
    const float* b1     = (const float*)d_in[4];
    const float* W2     = (const float*)d_in[5];
    const float* b2     = (const float*)d_in[6];
    float* out = (float*)d_out;

    splitmlp_kernel<<<GG, 128>>>(day, items, W1_day, W1_var, b1, W2, b2, out);
}

// round 5
// speedup vs baseline: 1.4950x; 1.1570x over previous
#include <cuda_runtime.h>

// SplitMLP: B=128, C=16, V=32, H=64, O=4, G=10000
// One CTA per group. Same blocking as R2 (warp = 16 hidden, lane = 4 batch
// rows) but all FMAs use packed fma.rn.f32x2 (FFMA2): 2 fp32 FMA per
// instruction, full fp32 precision, beating the 3-reg FFMA rt=2 ceiling.

#define BB 128
#define CC 16
#define VV 32
#define KK 48
#define HH 64
#define OO 4
#define GG 10000

#define W1S 68
#define ACTS 52
#define HS 68

#define S_W1_OFF 0
#define S_ACT_OFF 3264
#define S_BUF_FLOATS 9920   // max(phase1: 3264+6656, phase2: 128*68=8704)

typedef unsigned long long u64t;

__device__ __forceinline__ u64t pack2(float x, float y) {
    u64t p;
    asm("mov.b64 %0, {%1, %2};"
        : "=l"(p) : "r"(__float_as_uint(x)), "r"(__float_as_uint(y)));
    return p;
}
__device__ __forceinline__ void unpack2(u64t p, float& x, float& y) {
    unsigned int lo, hi;
    asm("mov.b64 {%0, %1}, %2;" : "=r"(lo), "=r"(hi) : "l"(p));
    x = __uint_as_float(lo); y = __uint_as_float(hi);
}
__device__ __forceinline__ void fma2(u64t& d, u64t a, u64t b) {
    asm("fma.rn.f32x2 %0, %1, %2, %3;" : "=l"(d) : "l"(a), "l"(b), "l"(d));
}

__global__ __launch_bounds__(128, 4) void splitmlp_kernel(
    const float* __restrict__ day,     // (B, C)
    const float* __restrict__ items,   // (B, G, V)
    const float* __restrict__ W1_day,  // (G, H, C)
    const float* __restrict__ W1_var,  // (G, H, V)
    const float* __restrict__ b1,      // (G, H)
    const float* __restrict__ W2,      // (G, O, H)
    const float* __restrict__ b2,      // (G, O)
    float* __restrict__ out)           // (B, G, O)
{
    __shared__ float s_buf[S_BUF_FLOATS];
    __shared__ float s_w2[OO * HH];
    __shared__ float s_b1[HH];
    __shared__ float s_b2[OO];

    float* const S_W1  = s_buf + S_W1_OFF;
    float* const S_ACT = s_buf + S_ACT_OFF;
    float* const S_H   = s_buf;            // phase-2 overlay

    const int g     = blockIdx.x;
    const int tid   = threadIdx.x;
    const int lane  = tid & 31;
    const int wj    = tid >> 5;
    const int jbase = wj * 16;

    // ---- staging ----
    {
        const float* p = W1_day + g * (HH * CC);
        #pragma unroll
        for (int i = tid; i < HH * CC; i += 128) {
            int j = i >> 4, c = i & 15;
            S_W1[c * W1S + j] = p[i];
        }
    }
    {
        const float* p = W1_var + g * (HH * VV);
        #pragma unroll
        for (int i = tid; i < HH * VV; i += 128) {
            int j = i >> 5, v = i & 31;
            S_W1[(CC + v) * W1S + j] = p[i];
        }
    }
    {
        const float* p = W2 + g * (OO * HH);
        #pragma unroll
        for (int i = tid; i < OO * HH; i += 128) s_w2[i] = p[i];
    }
    if (tid < HH) s_b1[tid] = b1[g * HH + tid];
    if (tid < OO) s_b2[tid] = b2[g * OO + tid];

    {
        const float4* p4 = (const float4*)day;
        #pragma unroll
        for (int i = tid; i < (BB * CC) / 4; i += 128) {
            int b = i >> 2, q = i & 3;
            *(float4*)&S_ACT[b * ACTS + q * 4] = p4[i];
        }
    }
    {
        const float4* p4 = (const float4*)items;
        #pragma unroll
        for (int i = tid; i < (BB * VV) / 4; i += 128) {
            int b = i >> 3, q = i & 7;
            *(float4*)&S_ACT[b * ACTS + CC + q * 4] =
                p4[(size_t)(b * GG + g) * 8 + q];
        }
    }
    __syncthreads();

    // ---- fc1: packed accumulators h2[r][p], p pairs hidden (2p, 2p+1) ----
    u64t h2[4][8];
    #pragma unroll
    for (int j4 = 0; j4 < 4; ++j4) {
        // bias float4 -> two pairs, replicated over rows
        ulonglong2 bp = *(const ulonglong2*)&s_b1[jbase + j4 * 4];
        #pragma unroll
        for (int r = 0; r < 4; ++r) {
            h2[r][j4 * 2 + 0] = bp.x;
            h2[r][j4 * 2 + 1] = bp.y;
        }
    }

    #pragma unroll 1
    for (int k4 = 0; k4 < KK; k4 += 4) {
        float a[4][4];
        #pragma unroll
        for (int r = 0; r < 4; ++r) {
            float4 t = *(const float4*)&S_ACT[(lane + 32 * r) * ACTS + k4];
            a[r][0] = t.x; a[r][1] = t.y; a[r][2] = t.z; a[r][3] = t.w;
        }
        #pragma unroll
        for (int kk = 0; kk < 4; ++kk) {
            u64t ap[4];
            #pragma unroll
            for (int r = 0; r < 4; ++r) ap[r] = pack2(a[r][kk], a[r][kk]);
            const float* wrow = &S_W1[(k4 + kk) * W1S + jbase];
            #pragma unroll
            for (int j4 = 0; j4 < 4; ++j4) {
                ulonglong2 wp = *(const ulonglong2*)&wrow[j4 * 4];
                #pragma unroll
                for (int r = 0; r < 4; ++r) {
                    fma2(h2[r][j4 * 2 + 0], ap[r], wp.x);
                    fma2(h2[r][j4 * 2 + 1], ap[r], wp.y);
                }
            }
        }
    }

    // ---- ReLU + store h to SMEM overlay ----
    __syncthreads();
    #pragma unroll
    for (int r = 0; r < 4; ++r) {
        int b = lane + 32 * r;
        #pragma unroll
        for (int j4 = 0; j4 < 4; ++j4) {
            float x0, x1, x2, x3;
            unpack2(h2[r][j4 * 2 + 0], x0, x1);
            unpack2(h2[r][j4 * 2 + 1], x2, x3);
            float4 t;
            t.x = fmaxf(x0, 0.0f); t.y = fmaxf(x1, 0.0f);
            t.z = fmaxf(x2, 0.0f); t.w = fmaxf(x3, 0.0f);
            *(float4*)&S_H[b * HS + jbase + j4 * 4] = t;
        }
    }
    __syncthreads();

    // ---- fc2: thread tid = batch row, packed dot products ----
    ulonglong2 hp[16];
    #pragma unroll
    for (int j4 = 0; j4 < 16; ++j4)
        hp[j4] = *(const ulonglong2*)&S_H[tid * HS + j4 * 4];

    float res[OO];
    #pragma unroll
    for (int o = 0; o < OO; ++o) {
        u64t acc0 = pack2(s_b2[o], 0.0f);
        u64t acc1 = 0ull;
        const float* w = &s_w2[o * HH];
        #pragma unroll
        for (int j4 = 0; j4 < 16; ++j4) {
            ulonglong2 wp = *(const ulonglong2*)&w[j4 * 4];
            fma2(acc0, hp[j4].x, wp.x);
            fma2(acc1, hp[j4].y, wp.y);
        }
        float l0, h0, l1, h1;
        unpack2(acc0, l0, h0);
        unpack2(acc1, l1, h1);
        res[o] = (l0 + h0) + (l1 + h1);
    }

    float4 r4;
    r4.x = res[0]; r4.y = res[1]; r4.z = res[2]; r4.w = res[3];
    ((float4*)out)[(size_t)tid * GG + g] = r4;
}

extern "C" void kernel_launch(void* const* d_in, const int* in_sizes, int n_in,
                              void* d_out, int out_size) {
    const float* day    = (const float*)d_in[0];
    const float* items  = (const float*)d_in[1];
    const float* W1_day = (const float*)d_in[2];
    const float* W1_var = (const float*)d_in[3];
    const float* b1     = (const float*)d_in[4];
    const float* W2     = (const float*)d_in[5];
    const float* b2     = (const float*)d_in[6];
    float* out = (float*)d_out;

    splitmlp_kernel<<<GG, 128>>>(day, items, W1_day, W1_var, b1, W2, b2, out);
}

// round 10
// speedup vs baseline: 3.3040x; 2.2100x over previous
#include <cuda_runtime.h>
#include <cstdint>

// SplitMLP via warp-level mma.sync (tf32), plain-sm_103-compatible PTX.
// Per group g (one CTA, 128 thr): D[128,64] = A[128x48] * W1[64x48]^T,
// bias+ReLU in accumulator registers, fc2 (O=4) via quad shfl reduction.

#define BB 128
#define CC 16
#define VV 32
#define KK 48
#define HH 64
#define OO 4
#define GG 10000

#define AS 52   // A row stride (floats): mult of 4, odd/4 -> conflict-free
#define WS 52   // W1 row stride

__device__ __forceinline__ uint32_t tf32r(float x) {
    uint32_t r;
    asm("cvt.rn.tf32.f32 %0, %1;" : "=r"(r) : "f"(x));
    return r;
}

__device__ __forceinline__ void mma16n8k8(float* d, const uint32_t* a,
                                          const uint32_t* b) {
    asm volatile(
        "mma.sync.aligned.m16n8k8.row.col.f32.tf32.tf32.f32 "
        "{%0,%1,%2,%3}, {%4,%5,%6,%7}, {%8,%9}, {%0,%1,%2,%3};"
        : "+f"(d[0]), "+f"(d[1]), "+f"(d[2]), "+f"(d[3])
        : "r"(a[0]), "r"(a[1]), "r"(a[2]), "r"(a[3]), "r"(b[0]), "r"(b[1]));
}

__global__ __launch_bounds__(128, 4) void splitmlp_kernel(
    const float* __restrict__ day,     // (B, C)
    const float* __restrict__ items,   // (B, G, V)
    const float* __restrict__ W1_day,  // (G, H, C)
    const float* __restrict__ W1_var,  // (G, H, V)
    const float* __restrict__ b1,      // (G, H)
    const float* __restrict__ W2,      // (G, O, H)
    const float* __restrict__ b2,      // (G, O)
    float* __restrict__ out)           // (B, G, O)
{
    __shared__ uint32_t s_a[BB * AS];     // tf32 A = [day | items_g], [b][k]
    __shared__ uint32_t s_w1[HH * WS];    // tf32 W1, [j][k]
    __shared__ float s_w2[OO * HH];
    __shared__ float s_b1[HH];
    __shared__ float s_b2[OO];

    const int g    = blockIdx.x;
    const int tid  = threadIdx.x;
    const int lane = tid & 31;
    const int wid  = tid >> 5;
    const int gid  = lane >> 2;   // row group within fragment
    const int tig  = lane & 3;    // thread-in-group (k / col subidx)

    // ---- staging (natural layouts, tf32 conversion) ----
    {
        const float4* p = (const float4*)(W1_day + (size_t)g * (HH * CC));
        #pragma unroll
        for (int i = tid; i < HH * CC / 4; i += 128) {
            int j = i >> 2, k = (i & 3) * 4;
            float4 t = p[i];
            uint4 u = { tf32r(t.x), tf32r(t.y), tf32r(t.z), tf32r(t.w) };
            *(uint4*)&s_w1[j * WS + k] = u;
        }
    }
    {
        const float4* p = (const float4*)(W1_var + (size_t)g * (HH * VV));
        #pragma unroll
        for (int i = tid; i < HH * VV / 4; i += 128) {
            int j = i >> 3, k = CC + (i & 7) * 4;
            float4 t = p[i];
            uint4 u = { tf32r(t.x), tf32r(t.y), tf32r(t.z), tf32r(t.w) };
            *(uint4*)&s_w1[j * WS + k] = u;
        }
    }
    {
        const float4* p = (const float4*)day;
        #pragma unroll
        for (int i = tid; i < BB * CC / 4; i += 128) {
            int b = i >> 2, k = (i & 3) * 4;
            float4 t = p[i];
            uint4 u = { tf32r(t.x), tf32r(t.y), tf32r(t.z), tf32r(t.w) };
            *(uint4*)&s_a[b * AS + k] = u;
        }
    }
    {
        const float4* p = (const float4*)items;
        #pragma unroll
        for (int i = tid; i < BB * VV / 4; i += 128) {
            int b = i >> 3, q = i & 7;
            float4 t = p[(size_t)(b * GG + g) * 8 + q];
            uint4 u = { tf32r(t.x), tf32r(t.y), tf32r(t.z), tf32r(t.w) };
            *(uint4*)&s_a[b * AS + CC + q * 4] = u;
        }
    }
    {
        const float4* p = (const float4*)(W2 + (size_t)g * (OO * HH));
        #pragma unroll
        for (int i = tid; i < OO * HH / 4; i += 128) ((float4*)s_w2)[i] = p[i];
    }
    if (tid < HH) s_b1[tid] = b1[(size_t)g * HH + tid];
    if (tid < OO) s_b2[tid] = b2[(size_t)g * OO + tid];
    __syncthreads();

    // ---- fc1 GEMM: warp wid owns rows [32*wid, 32*wid+32) ----
    const int m0 = wid * 32;
    float acc[2][8][4];
    #pragma unroll
    for (int t = 0; t < 2; ++t)
        #pragma unroll
        for (int n8 = 0; n8 < 8; ++n8)
            #pragma unroll
            for (int q = 0; q < 4; ++q) acc[t][n8][q] = 0.0f;

    #pragma unroll
    for (int kt = 0; kt < 6; ++kt) {
        const int k0 = kt * 8;
        uint32_t af[2][4];
        #pragma unroll
        for (int t = 0; t < 2; ++t) {
            int r0 = m0 + t * 16 + gid;
            af[t][0] = s_a[r0 * AS + k0 + tig];
            af[t][1] = s_a[(r0 + 8) * AS + k0 + tig];
            af[t][2] = s_a[r0 * AS + k0 + tig + 4];
            af[t][3] = s_a[(r0 + 8) * AS + k0 + tig + 4];
        }
        #pragma unroll
        for (int n8 = 0; n8 < 8; ++n8) {
            uint32_t bf[2];
            int n = n8 * 8 + gid;
            bf[0] = s_w1[n * WS + k0 + tig];
            bf[1] = s_w1[n * WS + k0 + tig + 4];
            mma16n8k8(acc[0][n8], af[0], bf);
            mma16n8k8(acc[1][n8], af[1], bf);
        }
    }

    // ---- epilogue: bias + ReLU in fragments ----
    // acc[t][n8][2*sub+d] -> row = m0+16t+8*sub+gid, col = 8*n8+2*tig+d
    #pragma unroll
    for (int n8 = 0; n8 < 8; ++n8) {
        float2 bv = *(const float2*)&s_b1[8 * n8 + 2 * tig];
        #pragma unroll
        for (int t = 0; t < 2; ++t) {
            acc[t][n8][0] = fmaxf(acc[t][n8][0] + bv.x, 0.0f);
            acc[t][n8][1] = fmaxf(acc[t][n8][1] + bv.y, 0.0f);
            acc[t][n8][2] = fmaxf(acc[t][n8][2] + bv.x, 0.0f);
            acc[t][n8][3] = fmaxf(acc[t][n8][3] + bv.y, 0.0f);
        }
    }

    // ---- fc2: per-thread partials over its 16 columns, quad reduce ----
    float res[2][2][OO];
    #pragma unroll
    for (int t = 0; t < 2; ++t)
        #pragma unroll
        for (int s = 0; s < 2; ++s)
            #pragma unroll
            for (int o = 0; o < OO; ++o) res[t][s][o] = 0.0f;

    #pragma unroll
    for (int o = 0; o < OO; ++o) {
        #pragma unroll
        for (int n8 = 0; n8 < 8; ++n8) {
            float2 wv = *(const float2*)&s_w2[o * HH + 8 * n8 + 2 * tig];
            #pragma unroll
            for (int t = 0; t < 2; ++t) {
                res[t][0][o] = fmaf(acc[t][n8][0], wv.x,
                               fmaf(acc[t][n8][1], wv.y, res[t][0][o]));
                res[t][1][o] = fmaf(acc[t][n8][2], wv.x,
                               fmaf(acc[t][n8][3], wv.y, res[t][1][o]));
            }
        }
    }

    #pragma unroll
    for (int t = 0; t < 2; ++t)
        #pragma unroll
        for (int s = 0; s < 2; ++s)
            #pragma unroll
            for (int o = 0; o < OO; ++o) {
                float v = res[t][s][o];
                v += __shfl_xor_sync(0xffffffffu, v, 1);
                v += __shfl_xor_sync(0xffffffffu, v, 2);
                res[t][s][o] = v;
            }

    if (tig == 0) {
        float4* outp = (float4*)out;
        #pragma unroll
        for (int t = 0; t < 2; ++t)
            #pragma unroll
            for (int s = 0; s < 2; ++s) {
                int row = m0 + 16 * t + 8 * s + gid;
                float4 o4;
                o4.x = res[t][s][0] + s_b2[0];
                o4.y = res[t][s][1] + s_b2[1];
                o4.z = res[t][s][2] + s_b2[2];
                o4.w = res[t][s][3] + s_b2[3];
                outp[(size_t)row * GG + g] = o4;
            }
    }
}

extern "C" void kernel_launch(void* const* d_in, const int* in_sizes, int n_in,
                              void* d_out, int out_size) {
    const float* day    = (const float*)d_in[0];
    const float* items  = (const float*)d_in[1];
    const float* W1_day = (const float*)d_in[2];
    const float* W1_var = (const float*)d_in[3];
    const float* b1     = (const float*)d_in[4];
    const float* W2     = (const float*)d_in[5];
    const float* b2     = (const float*)d_in[6];
    float* out = (float*)d_out;

    splitmlp_kernel<<<GG, 128>>>(day, items, W1_day, W1_var, b1, W2, b2, out);
}

// round 12
// speedup vs baseline: 3.4162x; 1.0340x over previous
#include <cuda_runtime.h>
#include <cstdint>

// SplitMLP, persistent double-buffered cp.async pipeline + mma.sync tf32.
// 296 persistent CTAs; CTA c handles groups c, c+296, ... For each group:
//   D[128,64] = A[128x48] * W1[64x48]^T (A = [day | items_g]),
//   bias+ReLU in fragments, fc2 (O=4) via quad shfl reduction.
// Weights/activations reach the MMA as raw f32 bits interpreted as tf32
// (round-toward-zero) -- CUTLASS-standard, no cvt needed.

#define CC 16
#define VV 32
#define HH 64
#define OO 4
#define GG 10000
#define NB 296

// float-index layout of dynamic SMEM
#define DAY_OFF   0
#define DAY_STR   20        // 16 + 4 pad (80 B rows)
#define BUF0_OFF  2560
#define BUF_FLOATS 8528
#define ITEMS_OFF 0
#define ITEMS_STR 36        // 32 + 4 pad (144 B rows)
#define W1V_OFF   4608
#define W1V_STR   36
#define W1D_OFF   6912
#define W1D_STR   20
#define W2_OFF    8192
#define B1_OFF    8448
#define B2_OFF    8512
#define SMEM_FLOATS (BUF0_OFF + 2 * BUF_FLOATS)   // 19616
#define SMEM_BYTES  (SMEM_FLOATS * 4)             // 78464

__device__ __forceinline__ void cpa16(uint32_t dst, const void* src) {
    asm volatile("cp.async.ca.shared.global [%0], [%1], 16;"
                 :: "r"(dst), "l"(__cvta_generic_to_global(src)));
}
__device__ __forceinline__ void cpa_commit() {
    asm volatile("cp.async.commit_group;");
}
template <int N>
__device__ __forceinline__ void cpa_wait() {
    asm volatile("cp.async.wait_group %0;" :: "n"(N));
}

__device__ __forceinline__ void mma16n8k8(float* d, const uint32_t* a,
                                          const uint32_t* b) {
    asm volatile(
        "mma.sync.aligned.m16n8k8.row.col.f32.tf32.tf32.f32 "
        "{%0,%1,%2,%3}, {%4,%5,%6,%7}, {%8,%9}, {%0,%1,%2,%3};"
        : "+f"(d[0]), "+f"(d[1]), "+f"(d[2]), "+f"(d[3])
        : "r"(a[0]), "r"(a[1]), "r"(a[2]), "r"(a[3]), "r"(b[0]), "r"(b[1]));
}

__global__ __launch_bounds__(128) void splitmlp_kernel(
    const float* __restrict__ day,     // (B, C)
    const float* __restrict__ items,   // (B, G, V)
    const float* __restrict__ W1_day,  // (G, H, C)
    const float* __restrict__ W1_var,  // (G, H, V)
    const float* __restrict__ b1,      // (G, H)
    const float* __restrict__ W2,      // (G, O, H)
    const float* __restrict__ b2,      // (G, O)
    float* __restrict__ out)           // (B, G, O)
{
    extern __shared__ float smf[];
    const uint32_t sb =
        (uint32_t)__cvta_generic_to_shared(smf);   // byte address of smem base
    const uint32_t* const smu = (const uint32_t*)smf;

    const int tid  = threadIdx.x;
    const int lane = tid & 31;
    const int wid  = tid >> 5;
    const int gid  = lane >> 2;
    const int tig  = lane & 3;

    // ---- stage a group into buffer `buf` via cp.async ----
    auto stage = [&](int buf, int g) {
        const uint32_t bo = sb + (BUF0_OFF + buf * BUF_FLOATS) * 4u;
        // items[:, g, :] : 128 rows x 8 chunks of 16B
        for (int ch = tid; ch < 1024; ch += 128) {
            int b = ch >> 3, q = ch & 7;
            cpa16(bo + (ITEMS_OFF + b * ITEMS_STR + q * 4) * 4u,
                  items + ((size_t)b * GG + g) * VV + q * 4);
        }
        // W1_var(g) : 64 rows x 8 chunks
        for (int ch = tid; ch < 512; ch += 128) {
            int j = ch >> 3, q = ch & 7;
            cpa16(bo + (W1V_OFF + j * W1V_STR + q * 4) * 4u,
                  W1_var + ((size_t)g * HH + j) * VV + q * 4);
        }
        // W1_day(g) : 64 rows x 4 chunks
        for (int ch = tid; ch < 256; ch += 128) {
            int j = ch >> 2, q = ch & 3;
            cpa16(bo + (W1D_OFF + j * W1D_STR + q * 4) * 4u,
                  W1_day + ((size_t)g * HH + j) * CC + q * 4);
        }
        // W2(g): 64 chunks; b1(g): 16 chunks; b2(g): 1 chunk
        if (tid < 64)
            cpa16(bo + (W2_OFF + tid * 4) * 4u, W2 + (size_t)g * 256 + tid * 4);
        else if (tid < 80)
            cpa16(bo + (B1_OFF + (tid - 64) * 4) * 4u,
                  b1 + (size_t)g * HH + (tid - 64) * 4);
        else if (tid == 80)
            cpa16(bo + B2_OFF * 4u, b2 + (size_t)g * OO);
    };

    // ---- prologue: stage first group, stage day (group-invariant) ----
    int g0 = blockIdx.x;
    if (g0 < GG) stage(0, g0);
    cpa_commit();
    {
        const float4* p = (const float4*)day;
        for (int i = tid; i < 128 * CC / 4; i += 128) {
            int b = i >> 2, q = i & 3;
            *(float4*)&smf[DAY_OFF + b * DAY_STR + q * 4] = p[i];
        }
    }

    int buf = 0;
    for (int g = g0; g < GG; g += NB) {
        const int gn = g + NB;
        if (gn < GG) stage(buf ^ 1, gn);
        cpa_commit();
        cpa_wait<1>();
        __syncthreads();

        const int bofl = BUF0_OFF + buf * BUF_FLOATS;
        const float* sb1 = smf + bofl + B1_OFF;
        const float* sb2 = smf + bofl + B2_OFF;
        const float* sw2 = smf + bofl + W2_OFF;

        // ---- fc1 GEMM: warp wid owns rows [32*wid, 32*wid+32) ----
        const int m0 = wid * 32;
        float acc[2][8][4];
        #pragma unroll
        for (int t = 0; t < 2; ++t)
            #pragma unroll
            for (int n8 = 0; n8 < 8; ++n8)
                #pragma unroll
                for (int q = 0; q < 4; ++q) acc[t][n8][q] = 0.0f;

        #pragma unroll
        for (int kt = 0; kt < 6; ++kt) {
            const uint32_t* abase;
            const uint32_t* bbase;
            int astr, bstr, k0;
            if (kt < 2) {
                abase = smu + DAY_OFF;        astr = DAY_STR;
                bbase = smu + bofl + W1D_OFF; bstr = W1D_STR;
                k0 = kt * 8;
            } else {
                abase = smu + bofl + ITEMS_OFF; astr = ITEMS_STR;
                bbase = smu + bofl + W1V_OFF;   bstr = W1V_STR;
                k0 = (kt - 2) * 8;
            }
            uint32_t af[2][4];
            #pragma unroll
            for (int t = 0; t < 2; ++t) {
                int r0 = m0 + t * 16 + gid;
                af[t][0] = abase[r0 * astr + k0 + tig];
                af[t][1] = abase[(r0 + 8) * astr + k0 + tig];
                af[t][2] = abase[r0 * astr + k0 + tig + 4];
                af[t][3] = abase[(r0 + 8) * astr + k0 + tig + 4];
            }
            #pragma unroll
            for (int n8 = 0; n8 < 8; ++n8) {
                uint32_t bf[2];
                int n = n8 * 8 + gid;
                bf[0] = bbase[n * bstr + k0 + tig];
                bf[1] = bbase[n * bstr + k0 + tig + 4];
                mma16n8k8(acc[0][n8], af[0], bf);
                mma16n8k8(acc[1][n8], af[1], bf);
            }
        }

        // ---- bias + ReLU in fragments ----
        #pragma unroll
        for (int n8 = 0; n8 < 8; ++n8) {
            float2 bv = *(const float2*)&sb1[8 * n8 + 2 * tig];
            #pragma unroll
            for (int t = 0; t < 2; ++t) {
                acc[t][n8][0] = fmaxf(acc[t][n8][0] + bv.x, 0.0f);
                acc[t][n8][1] = fmaxf(acc[t][n8][1] + bv.y, 0.0f);
                acc[t][n8][2] = fmaxf(acc[t][n8][2] + bv.x, 0.0f);
                acc[t][n8][3] = fmaxf(acc[t][n8][3] + bv.y, 0.0f);
            }
        }

        // ---- fc2: per-thread partials, quad reduce ----
        float res[2][2][OO];
        #pragma unroll
        for (int t = 0; t < 2; ++t)
            #pragma unroll
            for (int s = 0; s < 2; ++s)
                #pragma unroll
                for (int o = 0; o < OO; ++o) res[t][s][o] = 0.0f;

        #pragma unroll
        for (int o = 0; o < OO; ++o) {
            #pragma unroll
            for (int n8 = 0; n8 < 8; ++n8) {
                float2 wv = *(const float2*)&sw2[o * HH + 8 * n8 + 2 * tig];
                #pragma unroll
                for (int t = 0; t < 2; ++t) {
                    res[t][0][o] = fmaf(acc[t][n8][0], wv.x,
                                   fmaf(acc[t][n8][1], wv.y, res[t][0][o]));
                    res[t][1][o] = fmaf(acc[t][n8][2], wv.x,
                                   fmaf(acc[t][n8][3], wv.y, res[t][1][o]));
                }
            }
        }

        #pragma unroll
        for (int t = 0; t < 2; ++t)
            #pragma unroll
            for (int s = 0; s < 2; ++s)
                #pragma unroll
                for (int o = 0; o < OO; ++o) {
                    float v = res[t][s][o];
                    v += __shfl_xor_sync(0xffffffffu, v, 1);
                    v += __shfl_xor_sync(0xffffffffu, v, 2);
                    res[t][s][o] = v;
                }

        if (tig == 0) {
            float4* outp = (float4*)out;
            float4 bias2 = { sb2[0], sb2[1], sb2[2], sb2[3] };
            #pragma unroll
            for (int t = 0; t < 2; ++t)
                #pragma unroll
                for (int s = 0; s < 2; ++s) {
                    int row = m0 + 16 * t + 8 * s + gid;
                    float4 o4;
                    o4.x = res[t][s][0] + bias2.x;
                    o4.y = res[t][s][1] + bias2.y;
                    o4.z = res[t][s][2] + bias2.z;
                    o4.w = res[t][s][3] + bias2.w;
                    outp[(size_t)row * GG + g] = o4;
                }
        }

        __syncthreads();   // buffer reuse safety before next stage overwrite
        buf ^= 1;
    }
}

extern "C" void kernel_launch(void* const* d_in, const int* in_sizes, int n_in,
                              void* d_out, int out_size) {
    const float* day    = (const float*)d_in[0];
    const float* items  = (const float*)d_in[1];
    const float* W1_day = (const float*)d_in[2];
    const float* W1_var = (const float*)d_in[3];
    const float* b1     = (const float*)d_in[4];
    const float* W2     = (const float*)d_in[5];
    const float* b2     = (const float*)d_in[6];
    float* out = (float*)d_out;

    cudaFuncSetAttribute(splitmlp_kernel,
                         cudaFuncAttributeMaxDynamicSharedMemorySize,
                         SMEM_BYTES);
    splitmlp_kernel<<<NB, 128, SMEM_BYTES>>>(day, items, W1_day, W1_var, b1,
                                             W2, b2, out);
}